// round 1
// baseline (speedup 1.0000x reference)
#include <cuda_runtime.h>

#define N_VERT 500000
#define C 64
#define FE 9
#define NF 64
#define EPS 1e-5f

#define STATS_BLOCKS 2048
#define STATS_THREADS 256

// Scratch (static device globals; allocation-free per harness rules)
__device__ float g_partial[STATS_BLOCKS * 128];  // per block: 64 ch sums + 64 ch sumsq
__device__ float g_scale[C];
__device__ float g_shift[C];

// ---------------------------------------------------------------------------
// Kernel 1: per-channel partial sums / sums-of-squares (deterministic tree
// reduction; no float atomics so graph replays are bitwise stable).
// ---------------------------------------------------------------------------
__global__ void __launch_bounds__(STATS_THREADS)
stats_kernel(const float* __restrict__ lv) {
    const int tid = threadIdx.x;
    const long long total4 = (long long)N_VERT * C / 4;           // 8,000,000
    const long long stride = (long long)gridDim.x * blockDim.x;   // 524,288 (x4 floats % 64 == 0)
    long long i = (long long)blockIdx.x * blockDim.x + tid;

    float sx = 0.f, sy = 0.f, sz = 0.f, sw = 0.f;
    float qx = 0.f, qy = 0.f, qz = 0.f, qw = 0.f;
    const float4* lv4 = (const float4*)lv;
    for (; i < total4; i += stride) {
        float4 v = lv4[i];
        sx += v.x; sy += v.y; sz += v.z; sw += v.w;
        qx += v.x * v.x; qy += v.y * v.y; qz += v.z * v.z; qw += v.w * v.w;
    }

    // Thread's channel phase is fixed: c0 = (tid*4) % 64. Partner tid^16 has
    // the same channel phase -> pairwise reduce within the warp.
    sx += __shfl_xor_sync(0xffffffffu, sx, 16);
    sy += __shfl_xor_sync(0xffffffffu, sy, 16);
    sz += __shfl_xor_sync(0xffffffffu, sz, 16);
    sw += __shfl_xor_sync(0xffffffffu, sw, 16);
    qx += __shfl_xor_sync(0xffffffffu, qx, 16);
    qy += __shfl_xor_sync(0xffffffffu, qy, 16);
    qz += __shfl_xor_sync(0xffffffffu, qz, 16);
    qw += __shfl_xor_sync(0xffffffffu, qw, 16);

    __shared__ float shs[8][64];
    __shared__ float shq[8][64];
    const int wid = tid >> 5, lane = tid & 31;
    if (lane < 16) {
        const int c0 = lane * 4;  // ((wid*32+lane)*4) % 64 == lane*4
        shs[wid][c0 + 0] = sx; shs[wid][c0 + 1] = sy;
        shs[wid][c0 + 2] = sz; shs[wid][c0 + 3] = sw;
        shq[wid][c0 + 0] = qx; shq[wid][c0 + 1] = qy;
        shq[wid][c0 + 2] = qz; shq[wid][c0 + 3] = qw;
    }
    __syncthreads();
    if (tid < 64) {
        float s = 0.f, q = 0.f;
        #pragma unroll
        for (int w = 0; w < 8; w++) { s += shs[w][tid]; q += shq[w][tid]; }
        g_partial[blockIdx.x * 128 + tid]      = s;
        g_partial[blockIdx.x * 128 + 64 + tid] = q;
    }
}

// ---------------------------------------------------------------------------
// Kernel 2: finalize GroupNorm stats -> per-channel scale/shift
//   scale[c] = rstd[g] * gamma[c]
//   shift[c] = beta[c] - mean[g] * rstd[g] * gamma[c]
// ---------------------------------------------------------------------------
__global__ void finalize_kernel(const float* __restrict__ gamma,
                                const float* __restrict__ beta) {
    const int c = threadIdx.x;  // 0..63
    float s = 0.f, q = 0.f;
    for (int b = 0; b < STATS_BLOCKS; b++) {
        s += g_partial[b * 128 + c];
        q += g_partial[b * 128 + 64 + c];
    }
    __shared__ float shs[64], shq[64];
    shs[c] = s; shq[c] = q;
    __syncthreads();
    const int g = c >> 1;  // C/G == 2 channels per group
    const float gs = shs[2 * g] + shs[2 * g + 1];
    const float gq = shq[2 * g] + shq[2 * g + 1];
    const float inv = 1.0f / (2.0f * (float)N_VERT);
    const float mean = gs * inv;
    const float var  = gq * inv - mean * mean;
    const float rstd = rsqrtf(var + EPS);
    const float sc = rstd * gamma[c];
    g_scale[c] = sc;
    g_shift[c] = beta[c] - mean * sc;
}

// ---------------------------------------------------------------------------
// Kernel 3: fused gather(norm+relu) + GEMM.
// out[m, o] = bias[o] + sum_{f,c} relu(lv[nidx[m,f], c]*scale[c]+shift[c]) * W[f*64+c, o]
// Tile 64(M) x 64(N), K chunked per filter tap f (K=64 each, 9 taps).
// 256 threads, each computes a 4x4 micro-tile.
// ---------------------------------------------------------------------------
__global__ void __launch_bounds__(256)
gemm_kernel(const float* __restrict__ lv, const int* __restrict__ nidx,
            const float* __restrict__ W, const float* __restrict__ bias,
            float* __restrict__ out) {
    __shared__ float As[64][64];  // [k(channel)][m]
    __shared__ float Bs[64][64];  // [k][n]

    const int tid = threadIdx.x;
    const int m0 = blockIdx.x * 64;
    const int tx = tid & 15;      // output-col group (n)
    const int ty = tid >> 4;      // output-row group (m)

    // Loader mapping: 4 threads per vertex row, 16 channels each.
    const int lm = tid >> 2;           // 0..63 local row
    const int lc = (tid & 3) * 16;     // channel segment start
    int grow = m0 + lm;
    if (grow >= N_VERT) grow = N_VERT - 1;  // clamp (stores predicated later)

    // Per-thread GN affine constants (fixed channels across all f)
    float4 sc[4], sh[4];
    #pragma unroll
    for (int j = 0; j < 4; j++) {
        sc[j] = *(const float4*)&g_scale[lc + 4 * j];
        sh[j] = *(const float4*)&g_shift[lc + 4 * j];
    }

    float acc[4][4] = {};

    for (int f = 0; f < FE; f++) {
        const int vrow = nidx[grow * FE + f];
        const float4* src = (const float4*)(lv + (long long)vrow * C + lc);

        // Load B tile: W rows [f*64 .. f*64+63], 64 floats each.
        {
            const int kr = tid >> 2;
            const int n0 = (tid & 3) * 16;
            const float4* wsrc = (const float4*)(W + ((long long)(f * 64 + kr)) * NF + n0);
            float4* bdst = (float4*)&Bs[kr][n0];
            #pragma unroll
            for (int j = 0; j < 4; j++) bdst[j] = wsrc[j];
        }

        // Load + normalize + relu A tile (transposed into As[k][m]).
        #pragma unroll
        for (int j = 0; j < 4; j++) {
            float4 v = src[j];
            v.x = fmaxf(fmaf(v.x, sc[j].x, sh[j].x), 0.f);
            v.y = fmaxf(fmaf(v.y, sc[j].y, sh[j].y), 0.f);
            v.z = fmaxf(fmaf(v.z, sc[j].z, sh[j].z), 0.f);
            v.w = fmaxf(fmaf(v.w, sc[j].w, sh[j].w), 0.f);
            const int cb = lc + 4 * j;
            As[cb + 0][lm] = v.x;
            As[cb + 1][lm] = v.y;
            As[cb + 2][lm] = v.z;
            As[cb + 3][lm] = v.w;
        }
        __syncthreads();

        #pragma unroll
        for (int k = 0; k < 64; k++) {
            const float4 a = *(const float4*)&As[k][ty * 4];
            const float4 b = *(const float4*)&Bs[k][tx * 4];
            acc[0][0] = fmaf(a.x, b.x, acc[0][0]);
            acc[0][1] = fmaf(a.x, b.y, acc[0][1]);
            acc[0][2] = fmaf(a.x, b.z, acc[0][2]);
            acc[0][3] = fmaf(a.x, b.w, acc[0][3]);
            acc[1][0] = fmaf(a.y, b.x, acc[1][0]);
            acc[1][1] = fmaf(a.y, b.y, acc[1][1]);
            acc[1][2] = fmaf(a.y, b.z, acc[1][2]);
            acc[1][3] = fmaf(a.y, b.w, acc[1][3]);
            acc[2][0] = fmaf(a.z, b.x, acc[2][0]);
            acc[2][1] = fmaf(a.z, b.y, acc[2][1]);
            acc[2][2] = fmaf(a.z, b.z, acc[2][2]);
            acc[2][3] = fmaf(a.z, b.w, acc[2][3]);
            acc[3][0] = fmaf(a.w, b.x, acc[3][0]);
            acc[3][1] = fmaf(a.w, b.y, acc[3][1]);
            acc[3][2] = fmaf(a.w, b.z, acc[3][2]);
            acc[3][3] = fmaf(a.w, b.w, acc[3][3]);
        }
        __syncthreads();
    }

    // Epilogue: add bias, store (predicated on valid row).
    const float4 bb = *(const float4*)&bias[tx * 4];
    #pragma unroll
    for (int i = 0; i < 4; i++) {
        const int row = m0 + ty * 4 + i;
        if (row < N_VERT) {
            float4 o;
            o.x = acc[i][0] + bb.x;
            o.y = acc[i][1] + bb.y;
            o.z = acc[i][2] + bb.z;
            o.w = acc[i][3] + bb.w;
            *(float4*)&out[(long long)row * NF + tx * 4] = o;
        }
    }
}

// ---------------------------------------------------------------------------
// Launch
// ---------------------------------------------------------------------------
extern "C" void kernel_launch(void* const* d_in, const int* in_sizes, int n_in,
                              void* d_out, int out_size) {
    const float* lv        = (const float*)d_in[0];
    const int*   neigh_idx = (const int*)d_in[1];
    const float* gamma     = (const float*)d_in[2];
    const float* beta      = (const float*)d_in[3];
    const float* weight    = (const float*)d_in[4];
    const float* conv_bias = (const float*)d_in[5];
    float* out = (float*)d_out;

    stats_kernel<<<STATS_BLOCKS, STATS_THREADS>>>(lv);
    finalize_kernel<<<1, 64>>>(gamma, beta);
    const int gemm_blocks = (N_VERT + 63) / 64;  // 7813
    gemm_kernel<<<gemm_blocks, 256>>>(lv, neigh_idx, weight, conv_bias, out);
}

// round 2
// speedup vs baseline: 2.0285x; 2.0285x over previous
#include <cuda_runtime.h>

#define N_VERT 500000
#define C 64
#define FE 9
#define NF 64
#define EPS 1e-5f

#define STATS_BLOCKS 2048
#define STATS_THREADS 256

// Scratch (static device globals; allocation-free per harness rules)
__device__ float g_partial[STATS_BLOCKS * 128];  // per block: 64 ch sums + 64 ch sumsq
__device__ float g_scale[C];
__device__ float g_shift[C];
__device__ float g_xnorm[(long long)N_VERT * C];  // relu(groupnorm(lv)) precomputed

// ---------------------------------------------------------------------------
// Kernel 1: per-channel partial sums / sums-of-squares (deterministic).
// ---------------------------------------------------------------------------
__global__ void __launch_bounds__(STATS_THREADS)
stats_kernel(const float* __restrict__ lv) {
    const int tid = threadIdx.x;
    const long long total4 = (long long)N_VERT * C / 4;           // 8,000,000
    const long long stride = (long long)gridDim.x * blockDim.x;   // 524,288
    long long i = (long long)blockIdx.x * blockDim.x + tid;

    float sx = 0.f, sy = 0.f, sz = 0.f, sw = 0.f;
    float qx = 0.f, qy = 0.f, qz = 0.f, qw = 0.f;
    const float4* lv4 = (const float4*)lv;
    for (; i < total4; i += stride) {
        float4 v = lv4[i];
        sx += v.x; sy += v.y; sz += v.z; sw += v.w;
        qx += v.x * v.x; qy += v.y * v.y; qz += v.z * v.z; qw += v.w * v.w;
    }

    // Channel phase fixed per thread: c0 = (tid*4) % 64; partner tid^16 matches.
    sx += __shfl_xor_sync(0xffffffffu, sx, 16);
    sy += __shfl_xor_sync(0xffffffffu, sy, 16);
    sz += __shfl_xor_sync(0xffffffffu, sz, 16);
    sw += __shfl_xor_sync(0xffffffffu, sw, 16);
    qx += __shfl_xor_sync(0xffffffffu, qx, 16);
    qy += __shfl_xor_sync(0xffffffffu, qy, 16);
    qz += __shfl_xor_sync(0xffffffffu, qz, 16);
    qw += __shfl_xor_sync(0xffffffffu, qw, 16);

    __shared__ float shs[8][64];
    __shared__ float shq[8][64];
    const int wid = tid >> 5, lane = tid & 31;
    if (lane < 16) {
        const int c0 = lane * 4;
        shs[wid][c0 + 0] = sx; shs[wid][c0 + 1] = sy;
        shs[wid][c0 + 2] = sz; shs[wid][c0 + 3] = sw;
        shq[wid][c0 + 0] = qx; shq[wid][c0 + 1] = qy;
        shq[wid][c0 + 2] = qz; shq[wid][c0 + 3] = qw;
    }
    __syncthreads();
    if (tid < 64) {
        float s = 0.f, q = 0.f;
        #pragma unroll
        for (int w = 0; w < 8; w++) { s += shs[w][tid]; q += shq[w][tid]; }
        g_partial[blockIdx.x * 128 + tid]      = s;
        g_partial[blockIdx.x * 128 + 64 + tid] = q;
    }
}

// ---------------------------------------------------------------------------
// Kernel 2: finalize stats -> per-channel scale/shift
// ---------------------------------------------------------------------------
__global__ void finalize_kernel(const float* __restrict__ gamma,
                                const float* __restrict__ beta) {
    const int c = threadIdx.x;  // 0..63
    float s = 0.f, q = 0.f;
    for (int b = 0; b < STATS_BLOCKS; b++) {
        s += g_partial[b * 128 + c];
        q += g_partial[b * 128 + 64 + c];
    }
    __shared__ float shs[64], shq[64];
    shs[c] = s; shq[c] = q;
    __syncthreads();
    const int g = c >> 1;  // 2 channels per group
    const float gs = shs[2 * g] + shs[2 * g + 1];
    const float gq = shq[2 * g] + shq[2 * g + 1];
    const float inv = 1.0f / (2.0f * (float)N_VERT);
    const float mean = gs * inv;
    const float var  = gq * inv - mean * mean;
    const float rstd = rsqrtf(var + EPS);
    const float sc = rstd * gamma[c];
    g_scale[c] = sc;
    g_shift[c] = beta[c] - mean * sc;
}

// ---------------------------------------------------------------------------
// Kernel 3: x_norm = relu(gn(lv)) streamed once (removes 9x renorm in GEMM).
// ---------------------------------------------------------------------------
__global__ void __launch_bounds__(256)
norm_kernel(const float* __restrict__ lv) {
    const long long total4 = (long long)N_VERT * C / 4;
    const long long stride = (long long)gridDim.x * blockDim.x;  // multiple of 16
    long long i = (long long)blockIdx.x * blockDim.x + threadIdx.x;
    // Channel phase fixed: c0 = (i*4) % 64
    const int c0 = (int)((i & 15) * 4);
    const float4 sc = *(const float4*)&g_scale[c0];
    const float4 sh = *(const float4*)&g_shift[c0];
    const float4* src = (const float4*)lv;
    float4* dst = (float4*)g_xnorm;
    for (; i < total4; i += stride) {
        float4 v = src[i];
        v.x = fmaxf(fmaf(v.x, sc.x, sh.x), 0.f);
        v.y = fmaxf(fmaf(v.y, sc.y, sh.y), 0.f);
        v.z = fmaxf(fmaf(v.z, sc.z, sh.z), 0.f);
        v.w = fmaxf(fmaf(v.w, sc.w, sh.w), 0.f);
        dst[i] = v;
    }
}

// ---------------------------------------------------------------------------
// Kernel 4: gather + GEMM. Tile M=128, N=64, 128 threads, 8x8 micro-tiles.
// out[m,o] = bias[o] + sum_{f,c} x_norm[nidx[m,f], c] * W[f*64+c, o]
// ---------------------------------------------------------------------------
__global__ void __launch_bounds__(128)
gemm_kernel(const int* __restrict__ nidx,
            const float* __restrict__ W, const float* __restrict__ bias,
            float* __restrict__ out) {
    __shared__ float As[64][128];  // [k(channel)][m]  32 KB
    __shared__ float Bs[64][64];   // [k][n]           16 KB  (total 48 KB)

    const int tid = threadIdx.x;
    const int m0 = blockIdx.x * 128;
    const int tx = tid & 7;        // n group (8 cols each)
    const int ty = tid >> 3;       // m group (8 rows each)

    // A loader: one thread per row
    int grow = m0 + tid;
    if (grow >= N_VERT) grow = N_VERT - 1;  // clamp; stores predicated later

    // B loader mapping (bank-conflict-free STS.32): n = tid & 63, rows strided
    const int bn  = tid & 63;
    const int bk0 = tid >> 6;  // 0 or 1

    float acc[8][8] = {};

    for (int f = 0; f < FE; f++) {
        // ---- load A tile: gathered row -> As[k][m] (STS.32 coalesced) ----
        const int vrow = nidx[grow * FE + f];
        const float4* src = (const float4*)(g_xnorm + (long long)vrow * C);
        #pragma unroll
        for (int j = 0; j < 16; j++) {
            float4 v = src[j];
            As[4 * j + 0][tid] = v.x;
            As[4 * j + 1][tid] = v.y;
            As[4 * j + 2][tid] = v.z;
            As[4 * j + 3][tid] = v.w;
        }

        // ---- load B tile: W rows [f*64 .. f*64+63] ----
        {
            const float* wbase = W + (long long)f * 64 * NF + bn;
            #pragma unroll
            for (int r = 0; r < 32; r++) {
                const int kr = bk0 + 2 * r;
                Bs[kr][bn] = wbase[(long long)kr * NF];
            }
        }
        __syncthreads();

        // ---- 8x8 micro-tile FMA over k=64 ----
        #pragma unroll 8
        for (int k = 0; k < 64; k++) {
            float a[8], b[8];
            *(float4*)&a[0] = *(const float4*)&As[k][ty * 8];
            *(float4*)&a[4] = *(const float4*)&As[k][ty * 8 + 4];
            *(float4*)&b[0] = *(const float4*)&Bs[k][tx * 8];
            *(float4*)&b[4] = *(const float4*)&Bs[k][tx * 8 + 4];
            #pragma unroll
            for (int i = 0; i < 8; i++)
                #pragma unroll
                for (int j = 0; j < 8; j++)
                    acc[i][j] = fmaf(a[i], b[j], acc[i][j]);
        }
        __syncthreads();
    }

    // ---- epilogue: bias + store ----
    float4 bb0 = *(const float4*)&bias[tx * 8];
    float4 bb1 = *(const float4*)&bias[tx * 8 + 4];
    #pragma unroll
    for (int i = 0; i < 8; i++) {
        const int row = m0 + ty * 8 + i;
        if (row < N_VERT) {
            float4 o0, o1;
            o0.x = acc[i][0] + bb0.x; o0.y = acc[i][1] + bb0.y;
            o0.z = acc[i][2] + bb0.z; o0.w = acc[i][3] + bb0.w;
            o1.x = acc[i][4] + bb1.x; o1.y = acc[i][5] + bb1.y;
            o1.z = acc[i][6] + bb1.z; o1.w = acc[i][7] + bb1.w;
            float* orow = out + (long long)row * NF + tx * 8;
            *(float4*)orow = o0;
            *(float4*)(orow + 4) = o1;
        }
    }
}

// ---------------------------------------------------------------------------
// Launch
// ---------------------------------------------------------------------------
extern "C" void kernel_launch(void* const* d_in, const int* in_sizes, int n_in,
                              void* d_out, int out_size) {
    const float* lv        = (const float*)d_in[0];
    const int*   neigh_idx = (const int*)d_in[1];
    const float* gamma     = (const float*)d_in[2];
    const float* beta      = (const float*)d_in[3];
    const float* weight    = (const float*)d_in[4];
    const float* conv_bias = (const float*)d_in[5];
    float* out = (float*)d_out;

    stats_kernel<<<STATS_BLOCKS, STATS_THREADS>>>(lv);
    finalize_kernel<<<1, 64>>>(gamma, beta);
    norm_kernel<<<4096, 256>>>(lv);
    const int gemm_blocks = (N_VERT + 127) / 128;  // 3907
    gemm_kernel<<<gemm_blocks, 128>>>(neigh_idx, weight, conv_bias, out);
}

// round 4
// speedup vs baseline: 4.6038x; 2.2696x over previous
#include <cuda_runtime.h>
#include <cuda_fp16.h>
#include <cstdint>

#define N_VERT 500000
#define C 64
#define FE 9
#define NF 64
#define EPS 1e-5f

#define STATS_BLOCKS 2048
#define STATS_THREADS 256
#define N_TILES ((N_VERT + 127) / 128)   // 3907
#define GEMM_GRID 148

// ---------------------------------------------------------------------------
// Device scratch (allocation-free)
// ---------------------------------------------------------------------------
__device__ float  g_partial[STATS_BLOCKS * 128];
__device__ float  g_scale[C];
__device__ float  g_shift[C];
__device__ __half g_xh[(size_t)N_VERT * C];     // fp16(relu(gn(lv)))  64 MB
// W pre-shuffled into mma.sync B-fragment lane order, hi/lo fp16 split.
// Layout: chunk = (f*4 + ks)*8 + nb  (f tap, ks k16-step, nb n8-block)
//         per chunk: 32 lanes x uint2 (4 halves: k0,k1,k0+8,k1+8 at n=nb*8+lane/4)
__device__ uint4 g_wfh[FE * 4 * 8 * 32 / 2];    // 9216 uint2 = 4608 uint4 = 73728 B
__device__ uint4 g_wfl[FE * 4 * 8 * 32 / 2];

// SMEM offsets (relative to 128B-aligned base)
#define OFF_BHI 0
#define OFF_BLO 73728
#define OFF_A0  147456
#define OFF_A1  163840
#define SMEM_BYTES (180224 + 128)

__device__ __forceinline__ uint32_t swz(uint32_t off) { return off ^ ((off >> 3) & 0x70); }

__device__ __forceinline__ void mma16816(float* d, const uint32_t* a, uint2 b) {
    asm volatile(
        "mma.sync.aligned.m16n8k16.row.col.f32.f16.f16.f32 "
        "{%0,%1,%2,%3}, {%4,%5,%6,%7}, {%8,%9}, {%0,%1,%2,%3};"
        : "+f"(d[0]), "+f"(d[1]), "+f"(d[2]), "+f"(d[3])
        : "r"(a[0]), "r"(a[1]), "r"(a[2]), "r"(a[3]), "r"(b.x), "r"(b.y));
}

// ---------------------------------------------------------------------------
// Kernel 1: per-channel partial sums (deterministic)
// ---------------------------------------------------------------------------
__global__ void __launch_bounds__(STATS_THREADS)
stats_kernel(const float* __restrict__ lv) {
    const int tid = threadIdx.x;
    const long long total4 = (long long)N_VERT * C / 4;
    const long long stride = (long long)gridDim.x * blockDim.x;
    long long i = (long long)blockIdx.x * blockDim.x + tid;

    float sx = 0.f, sy = 0.f, sz = 0.f, sw = 0.f;
    float qx = 0.f, qy = 0.f, qz = 0.f, qw = 0.f;
    const float4* lv4 = (const float4*)lv;
    for (; i < total4; i += stride) {
        float4 v = lv4[i];
        sx += v.x; sy += v.y; sz += v.z; sw += v.w;
        qx += v.x * v.x; qy += v.y * v.y; qz += v.z * v.z; qw += v.w * v.w;
    }
    sx += __shfl_xor_sync(0xffffffffu, sx, 16);
    sy += __shfl_xor_sync(0xffffffffu, sy, 16);
    sz += __shfl_xor_sync(0xffffffffu, sz, 16);
    sw += __shfl_xor_sync(0xffffffffu, sw, 16);
    qx += __shfl_xor_sync(0xffffffffu, qx, 16);
    qy += __shfl_xor_sync(0xffffffffu, qy, 16);
    qz += __shfl_xor_sync(0xffffffffu, qz, 16);
    qw += __shfl_xor_sync(0xffffffffu, qw, 16);

    __shared__ float shs[8][64];
    __shared__ float shq[8][64];
    const int wid = tid >> 5, lane = tid & 31;
    if (lane < 16) {
        const int c0 = lane * 4;
        shs[wid][c0 + 0] = sx; shs[wid][c0 + 1] = sy;
        shs[wid][c0 + 2] = sz; shs[wid][c0 + 3] = sw;
        shq[wid][c0 + 0] = qx; shq[wid][c0 + 1] = qy;
        shq[wid][c0 + 2] = qz; shq[wid][c0 + 3] = qw;
    }
    __syncthreads();
    if (tid < 64) {
        float s = 0.f, q = 0.f;
        #pragma unroll
        for (int w = 0; w < 8; w++) { s += shs[w][tid]; q += shq[w][tid]; }
        g_partial[blockIdx.x * 128 + tid]      = s;
        g_partial[blockIdx.x * 128 + 64 + tid] = q;
    }
}

// ---------------------------------------------------------------------------
// Kernel 2: finalize -> scale/shift
// ---------------------------------------------------------------------------
__global__ void finalize_kernel(const float* __restrict__ gamma,
                                const float* __restrict__ beta) {
    const int c = threadIdx.x;
    float s = 0.f, q = 0.f;
    for (int b = 0; b < STATS_BLOCKS; b++) {
        s += g_partial[b * 128 + c];
        q += g_partial[b * 128 + 64 + c];
    }
    __shared__ float shs[64], shq[64];
    shs[c] = s; shq[c] = q;
    __syncthreads();
    const int g = c >> 1;
    const float gs = shs[2 * g] + shs[2 * g + 1];
    const float gq = shq[2 * g] + shq[2 * g + 1];
    const float inv = 1.0f / (2.0f * (float)N_VERT);
    const float mean = gs * inv;
    const float var  = gq * inv - mean * mean;
    const float rstd = rsqrtf(var + EPS);
    const float sc = rstd * gamma[c];
    g_scale[c] = sc;
    g_shift[c] = beta[c] - mean * sc;
}

// ---------------------------------------------------------------------------
// Kernel 3: xh = fp16(relu(gn(lv)))
// ---------------------------------------------------------------------------
__global__ void __launch_bounds__(256)
convert_kernel(const float* __restrict__ lv) {
    const long long total4 = (long long)N_VERT * C / 4;
    const long long stride = (long long)gridDim.x * blockDim.x;
    long long i = (long long)blockIdx.x * blockDim.x + threadIdx.x;
    const int c0 = (int)((i & 15) * 4);
    const float4 sc = *(const float4*)&g_scale[c0];
    const float4 sh = *(const float4*)&g_shift[c0];
    const float4* src = (const float4*)lv;
    uint2* dst = (uint2*)g_xh;
    for (; i < total4; i += stride) {
        float4 v = src[i];
        v.x = fmaxf(fmaf(v.x, sc.x, sh.x), 0.f);
        v.y = fmaxf(fmaf(v.y, sc.y, sh.y), 0.f);
        v.z = fmaxf(fmaf(v.z, sc.z, sh.z), 0.f);
        v.w = fmaxf(fmaf(v.w, sc.w, sh.w), 0.f);
        union { uint2 u; __half2 h[2]; } pk;
        pk.h[0] = __floats2half2_rn(v.x, v.y);
        pk.h[1] = __floats2half2_rn(v.z, v.w);
        dst[i] = pk.u;
    }
}

// ---------------------------------------------------------------------------
// Kernel 4: W -> fragment-ordered hi/lo fp16 splits.
// One thread per (chunk, lane): 9216 threads.
// ---------------------------------------------------------------------------
__global__ void wfrag_kernel(const float* __restrict__ W) {
    const int t = blockIdx.x * blockDim.x + threadIdx.x;
    if (t >= FE * 4 * 8 * 32) return;
    const int lane  = t & 31;
    const int chunk = t >> 5;
    const int nb = chunk & 7;
    const int ks = (chunk >> 3) & 3;
    const int f  = chunk >> 5;
    const int n  = nb * 8 + (lane >> 2);
    const int k0 = ks * 16 + 2 * (lane & 3);

    float w0 = W[(long long)(f * C + k0 + 0) * NF + n];
    float w1 = W[(long long)(f * C + k0 + 1) * NF + n];
    float w2 = W[(long long)(f * C + k0 + 8) * NF + n];
    float w3 = W[(long long)(f * C + k0 + 9) * NF + n];

    __half h0 = __float2half_rn(w0), h1 = __float2half_rn(w1);
    __half h2 = __float2half_rn(w2), h3 = __float2half_rn(w3);
    __half l0 = __float2half_rn(w0 - __half2float(h0));
    __half l1 = __float2half_rn(w1 - __half2float(h1));
    __half l2 = __float2half_rn(w2 - __half2float(h2));
    __half l3 = __float2half_rn(w3 - __half2float(h3));

    union { uint2 u; __half2 h[2]; } hi, lo;
    hi.h[0] = __halves2half2(h0, h1); hi.h[1] = __halves2half2(h2, h3);
    lo.h[0] = __halves2half2(l0, l1); lo.h[1] = __halves2half2(l2, l3);
    ((uint2*)g_wfh)[t] = hi.u;
    ((uint2*)g_wfl)[t] = lo.u;
}

// ---------------------------------------------------------------------------
// Kernel 5: persistent HMMA GEMM with gather.
// 256 threads = 8 warps; warp (wm = wid&3, wn = wid>>2) owns out[wm*32+.., wn*32+..]
// ---------------------------------------------------------------------------
__global__ void __launch_bounds__(256)
gemm_mma_kernel(const int* __restrict__ nidx, const float* __restrict__ bias,
                float* __restrict__ out) {
    extern __shared__ char dsm[];
    // 128B-align base (bank pattern + uint4 alignment)
    char* SB = (char*)(((uintptr_t)dsm + 127) & ~(uintptr_t)127);

    const int tid = threadIdx.x;
    const int wid = tid >> 5;
    const int lid = tid & 31;
    const int wm = wid & 3;        // m 32-block
    const int wn = wid >> 2;       // n 32-block (0/1)
    const int n0 = wn * 32;
    const int gr = lid >> 2;       // 0..7
    const int qc = lid & 3;        // quad col

    // --- stage W fragments into SMEM (hi 72KB + lo 72KB) ---
    {
        uint4* bh = (uint4*)(SB + OFF_BHI);
        uint4* bl = (uint4*)(SB + OFF_BLO);
        #pragma unroll
        for (int i = tid; i < 4608; i += 256) { bh[i] = g_wfh[i]; bl[i] = g_wfl[i]; }
    }

    // per-lane bias pairs for the 4 n8 blocks
    float2 bb[4];
    #pragma unroll
    for (int nb = 0; nb < 4; nb++)
        bb[nb] = *(const float2*)(bias + n0 + nb * 8 + qc * 2);

    __syncthreads();

    const uint4* xh4 = (const uint4*)g_xh;
    const int arow = tid >> 1;       // 0..127 local row for gather
    const int ah   = tid & 1;        // row half (32 halves = 64B)

    for (int t = blockIdx.x; t < N_TILES; t += gridDim.x) {
        const int m0 = t * 128;
        int grow = m0 + arow; if (grow >= N_VERT) grow = N_VERT - 1;

        float acc[2][4][4];
        #pragma unroll
        for (int mt = 0; mt < 2; mt++)
            #pragma unroll
            for (int nb = 0; nb < 4; nb++)
                #pragma unroll
                for (int j = 0; j < 4; j++) acc[mt][nb][j] = 0.f;

        // prefetch tap 0
        uint4 rcur[4], rnxt[4];
        {
            const int i0 = nidx[(long long)grow * FE + 0];
            const uint4* src = xh4 + (size_t)i0 * 8 + ah * 4;
            #pragma unroll
            for (int j = 0; j < 4; j++) rcur[j] = src[j];
        }

        #pragma unroll
        for (int f = 0; f < FE; f++) {
            const int buf = f & 1;
            char* ab = SB + (buf ? OFF_A1 : OFF_A0);
            // store gathered rows (SW128 swizzled)
            #pragma unroll
            for (int j = 0; j < 4; j++)
                *(uint4*)(ab + swz((uint32_t)(arow * 128 + ah * 64 + j * 16))) = rcur[j];

            // prefetch next tap
            if (f < FE - 1) {
                const int i1 = nidx[(long long)grow * FE + f + 1];
                const uint4* src = xh4 + (size_t)i1 * 8 + ah * 4;
                #pragma unroll
                for (int j = 0; j < 4; j++) rnxt[j] = src[j];
            }
            __syncthreads();   // A[buf] visible; prev-prev mma on A[buf] done

            // compute on A[buf]
            const char* abr = SB + (buf ? OFF_A1 : OFF_A0);
            const char* bhc = SB + OFF_BHI;
            const char* blc = SB + OFF_BLO;
            #pragma unroll
            for (int ks = 0; ks < 4; ks++) {
                uint32_t afr[2][4];
                #pragma unroll
                for (int mt = 0; mt < 2; mt++) {
                    const int r0 = wm * 32 + mt * 16 + gr;
                    const uint32_t cb = (uint32_t)(ks * 32 + qc * 4);
                    afr[mt][0] = *(const uint32_t*)(abr + swz(r0 * 128 + cb));
                    afr[mt][1] = *(const uint32_t*)(abr + swz((r0 + 8) * 128 + cb));
                    afr[mt][2] = *(const uint32_t*)(abr + swz(r0 * 128 + cb + 16));
                    afr[mt][3] = *(const uint32_t*)(abr + swz((r0 + 8) * 128 + cb + 16));
                }
                #pragma unroll
                for (int nb = 0; nb < 4; nb++) {
                    const int chunk = (f * 4 + ks) * 8 + wn * 4 + nb;
                    const uint2 bhf = *(const uint2*)(bhc + (chunk * 32 + lid) * 8);
                    const uint2 blf = *(const uint2*)(blc + (chunk * 32 + lid) * 8);
                    #pragma unroll
                    for (int mt = 0; mt < 2; mt++) {
                        mma16816(acc[mt][nb], afr[mt], bhf);
                        mma16816(acc[mt][nb], afr[mt], blf);
                    }
                }
            }
            #pragma unroll
            for (int j = 0; j < 4; j++) rcur[j] = rnxt[j];
        }

        // --- epilogue: bias + direct STG (float2 per fragment row) ---
        #pragma unroll
        for (int mt = 0; mt < 2; mt++) {
            const int r0 = m0 + wm * 32 + mt * 16 + gr;
            #pragma unroll
            for (int nb = 0; nb < 4; nb++) {
                const int col = n0 + nb * 8 + qc * 2;
                if (r0 < N_VERT) {
                    float2 v; v.x = acc[mt][nb][0] + bb[nb].x;
                              v.y = acc[mt][nb][1] + bb[nb].y;
                    *(float2*)(out + (long long)r0 * NF + col) = v;
                }
                if (r0 + 8 < N_VERT) {
                    float2 v; v.x = acc[mt][nb][2] + bb[nb].x;
                              v.y = acc[mt][nb][3] + bb[nb].y;
                    *(float2*)(out + (long long)(r0 + 8) * NF + col) = v;
                }
            }
        }
        __syncthreads();   // protect A buffers before next tile's first store
    }
}

// ---------------------------------------------------------------------------
// Launch
// ---------------------------------------------------------------------------
extern "C" void kernel_launch(void* const* d_in, const int* in_sizes, int n_in,
                              void* d_out, int out_size) {
    const float* lv        = (const float*)d_in[0];
    const int*   neigh_idx = (const int*)d_in[1];
    const float* gamma     = (const float*)d_in[2];
    const float* beta      = (const float*)d_in[3];
    const float* weight    = (const float*)d_in[4];
    const float* conv_bias = (const float*)d_in[5];
    float* out = (float*)d_out;

    cudaFuncSetAttribute(gemm_mma_kernel,
                         cudaFuncAttributeMaxDynamicSharedMemorySize, SMEM_BYTES);

    stats_kernel<<<STATS_BLOCKS, STATS_THREADS>>>(lv);
    finalize_kernel<<<1, 64>>>(gamma, beta);
    convert_kernel<<<4096, 256>>>(lv);
    wfrag_kernel<<<(FE * 4 * 8 * 32 + 255) / 256, 256>>>(weight);
    gemm_mma_kernel<<<GEMM_GRID, 256, SMEM_BYTES>>>(neigh_idx, conv_bias, out);
}

// round 5
// speedup vs baseline: 5.7196x; 1.2424x over previous
#include <cuda_runtime.h>
#include <cuda_fp16.h>
#include <cstdint>

#define N_VERT 500000
#define C 64
#define FE 9
#define NF 64
#define EPS 1e-5f

#define STATS_BLOCKS 2048
#define STATS_THREADS 256
#define N_TILES ((N_VERT + 127) / 128)   // 3907
#define GEMM_GRID 148

// ---------------------------------------------------------------------------
// Device scratch (allocation-free)
// ---------------------------------------------------------------------------
__device__ float  g_partial[STATS_BLOCKS * 128];
__device__ float  g_scale[C];
__device__ float  g_shift[C];
__device__ __half g_xh[(size_t)N_VERT * C];     // fp16(relu(gn(lv)))  64 MB
// W fragments, hi/lo interleaved: uint4 = {hi.x, hi.y, lo.x, lo.y}
// chunk = (f*4 + ks)*8 + nb ; index t = chunk*32 + lane
__device__ uint4 g_wf[FE * 4 * 8 * 32];         // 9216 uint4 = 147456 B

// SMEM layout (dynamic, 128B-aligned base)
#define OFF_B    0
#define B_BYTES  147456
#define OFF_A    147456
#define A_STAGE  16384
#define SMEM_BYTES (147456 + 4 * 16384 + 128)   // 213120 < 227KB

__device__ __forceinline__ uint32_t swz(uint32_t off) { return off ^ ((off >> 3) & 0x70); }

__device__ __forceinline__ uint32_t smem_u32(const void* p) {
    uint32_t a;
    asm("{ .reg .u64 t; cvta.to.shared.u64 t, %1; cvt.u32.u64 %0, t; }"
        : "=r"(a) : "l"(p));
    return a;
}
__device__ __forceinline__ void cp_async16(uint32_t dst, const void* src) {
    asm volatile("cp.async.cg.shared.global [%0], [%1], 16;"
                 :: "r"(dst), "l"(src) : "memory");
}
__device__ __forceinline__ void cp_commit() {
    asm volatile("cp.async.commit_group;" ::: "memory");
}
template <int N>
__device__ __forceinline__ void cp_wait() {
    asm volatile("cp.async.wait_group %0;" :: "n"(N) : "memory");
}
__device__ __forceinline__ void ldmatrix_x4(uint32_t* r, uint32_t addr) {
    asm volatile("ldmatrix.sync.aligned.m8n8.x4.shared.b16 {%0,%1,%2,%3}, [%4];"
                 : "=r"(r[0]), "=r"(r[1]), "=r"(r[2]), "=r"(r[3]) : "r"(addr));
}
__device__ __forceinline__ void mma16816(float* d, const uint32_t* a, uint32_t b0, uint32_t b1) {
    asm volatile(
        "mma.sync.aligned.m16n8k16.row.col.f32.f16.f16.f32 "
        "{%0,%1,%2,%3}, {%4,%5,%6,%7}, {%8,%9}, {%0,%1,%2,%3};"
        : "+f"(d[0]), "+f"(d[1]), "+f"(d[2]), "+f"(d[3])
        : "r"(a[0]), "r"(a[1]), "r"(a[2]), "r"(a[3]), "r"(b0), "r"(b1));
}

// ---------------------------------------------------------------------------
// Kernel 1: per-channel partial sums (deterministic)
// ---------------------------------------------------------------------------
__global__ void __launch_bounds__(STATS_THREADS)
stats_kernel(const float* __restrict__ lv) {
    const int tid = threadIdx.x;
    const long long total4 = (long long)N_VERT * C / 4;
    const long long stride = (long long)gridDim.x * blockDim.x;
    long long i = (long long)blockIdx.x * blockDim.x + tid;

    float sx = 0.f, sy = 0.f, sz = 0.f, sw = 0.f;
    float qx = 0.f, qy = 0.f, qz = 0.f, qw = 0.f;
    const float4* lv4 = (const float4*)lv;
    for (; i < total4; i += stride) {
        float4 v = lv4[i];
        sx += v.x; sy += v.y; sz += v.z; sw += v.w;
        qx += v.x * v.x; qy += v.y * v.y; qz += v.z * v.z; qw += v.w * v.w;
    }
    sx += __shfl_xor_sync(0xffffffffu, sx, 16);
    sy += __shfl_xor_sync(0xffffffffu, sy, 16);
    sz += __shfl_xor_sync(0xffffffffu, sz, 16);
    sw += __shfl_xor_sync(0xffffffffu, sw, 16);
    qx += __shfl_xor_sync(0xffffffffu, qx, 16);
    qy += __shfl_xor_sync(0xffffffffu, qy, 16);
    qz += __shfl_xor_sync(0xffffffffu, qz, 16);
    qw += __shfl_xor_sync(0xffffffffu, qw, 16);

    __shared__ float shs[8][64];
    __shared__ float shq[8][64];
    const int wid = tid >> 5, lane = tid & 31;
    if (lane < 16) {
        const int c0 = lane * 4;
        shs[wid][c0 + 0] = sx; shs[wid][c0 + 1] = sy;
        shs[wid][c0 + 2] = sz; shs[wid][c0 + 3] = sw;
        shq[wid][c0 + 0] = qx; shq[wid][c0 + 1] = qy;
        shq[wid][c0 + 2] = qz; shq[wid][c0 + 3] = qw;
    }
    __syncthreads();
    if (tid < 64) {
        float s = 0.f, q = 0.f;
        #pragma unroll
        for (int w = 0; w < 8; w++) { s += shs[w][tid]; q += shq[w][tid]; }
        g_partial[blockIdx.x * 128 + tid]      = s;
        g_partial[blockIdx.x * 128 + 64 + tid] = q;
    }
}

// ---------------------------------------------------------------------------
// Kernel 2: finalize -> scale/shift
// ---------------------------------------------------------------------------
__global__ void finalize_kernel(const float* __restrict__ gamma,
                                const float* __restrict__ beta) {
    const int c = threadIdx.x;
    float s = 0.f, q = 0.f;
    for (int b = 0; b < STATS_BLOCKS; b++) {
        s += g_partial[b * 128 + c];
        q += g_partial[b * 128 + 64 + c];
    }
    __shared__ float shs[64], shq[64];
    shs[c] = s; shq[c] = q;
    __syncthreads();
    const int g = c >> 1;
    const float gs = shs[2 * g] + shs[2 * g + 1];
    const float gq = shq[2 * g] + shq[2 * g + 1];
    const float inv = 1.0f / (2.0f * (float)N_VERT);
    const float mean = gs * inv;
    const float var  = gq * inv - mean * mean;
    const float rstd = rsqrtf(var + EPS);
    const float sc = rstd * gamma[c];
    g_scale[c] = sc;
    g_shift[c] = beta[c] - mean * sc;
}

// ---------------------------------------------------------------------------
// Kernel 3: xh = fp16(relu(gn(lv)))
// ---------------------------------------------------------------------------
__global__ void __launch_bounds__(256)
convert_kernel(const float* __restrict__ lv) {
    const long long total4 = (long long)N_VERT * C / 4;
    const long long stride = (long long)gridDim.x * blockDim.x;
    long long i = (long long)blockIdx.x * blockDim.x + threadIdx.x;
    const int c0 = (int)((i & 15) * 4);
    const float4 sc = *(const float4*)&g_scale[c0];
    const float4 sh = *(const float4*)&g_shift[c0];
    const float4* src = (const float4*)lv;
    uint2* dst = (uint2*)g_xh;
    for (; i < total4; i += stride) {
        float4 v = src[i];
        v.x = fmaxf(fmaf(v.x, sc.x, sh.x), 0.f);
        v.y = fmaxf(fmaf(v.y, sc.y, sh.y), 0.f);
        v.z = fmaxf(fmaf(v.z, sc.z, sh.z), 0.f);
        v.w = fmaxf(fmaf(v.w, sc.w, sh.w), 0.f);
        union { uint2 u; __half2 h[2]; } pk;
        pk.h[0] = __floats2half2_rn(v.x, v.y);
        pk.h[1] = __floats2half2_rn(v.z, v.w);
        dst[i] = pk.u;
    }
}

// ---------------------------------------------------------------------------
// Kernel 4: W -> fragment-ordered, hi/lo interleaved uint4
// ---------------------------------------------------------------------------
__global__ void wfrag_kernel(const float* __restrict__ W) {
    const int t = blockIdx.x * blockDim.x + threadIdx.x;
    if (t >= FE * 4 * 8 * 32) return;
    const int lane  = t & 31;
    const int chunk = t >> 5;
    const int nb = chunk & 7;
    const int ks = (chunk >> 3) & 3;
    const int f  = chunk >> 5;
    const int n  = nb * 8 + (lane >> 2);
    const int k0 = ks * 16 + 2 * (lane & 3);

    float w0 = W[(long long)(f * C + k0 + 0) * NF + n];
    float w1 = W[(long long)(f * C + k0 + 1) * NF + n];
    float w2 = W[(long long)(f * C + k0 + 8) * NF + n];
    float w3 = W[(long long)(f * C + k0 + 9) * NF + n];

    __half h0 = __float2half_rn(w0), h1 = __float2half_rn(w1);
    __half h2 = __float2half_rn(w2), h3 = __float2half_rn(w3);
    __half l0 = __float2half_rn(w0 - __half2float(h0));
    __half l1 = __float2half_rn(w1 - __half2float(h1));
    __half l2 = __float2half_rn(w2 - __half2float(h2));
    __half l3 = __float2half_rn(w3 - __half2float(h3));

    union { uint4 u; __half2 h[4]; } pk;
    pk.h[0] = __halves2half2(h0, h1); pk.h[1] = __halves2half2(h2, h3);
    pk.h[2] = __halves2half2(l0, l1); pk.h[3] = __halves2half2(l2, l3);
    g_wf[t] = pk.u;
}

// ---------------------------------------------------------------------------
// Kernel 5: persistent HMMA GEMM, cp.async 4-stage tap pipeline + ldmatrix.
// ---------------------------------------------------------------------------
__global__ void __launch_bounds__(256)
gemm_mma_kernel(const int* __restrict__ nidx, const float* __restrict__ bias,
                float* __restrict__ out) {
    extern __shared__ char dsm[];
    char* SB = (char*)(((uintptr_t)dsm + 127) & ~(uintptr_t)127);
    const uint32_t sb = smem_u32(SB);

    const int tid = threadIdx.x;
    const int wid = tid >> 5;
    const int lid = tid & 31;
    const int wm = wid & 3;        // m 32-block
    const int wn = wid >> 2;       // n 32-block (0/1)
    const int n0 = wn * 32;
    const int qc = lid & 3;

    // --- stage W fragments into SMEM (144 KB, once) ---
    {
        uint4* bsm = (uint4*)(SB + OFF_B);
        for (int i = tid; i < 9216; i += 256) bsm[i] = g_wf[i];
    }

    float2 bb[4];
    #pragma unroll
    for (int nb = 0; nb < 4; nb++)
        bb[nb] = *(const float2*)(bias + n0 + nb * 8 + qc * 2);

    __syncthreads();

    // gather-fill mapping: thread covers row = tid>>1, 64B half = tid&1
    const int arow = tid >> 1;
    const int ahf  = tid & 1;

    // ldmatrix per-lane address components (fixed per thread)
    const int lrow8 = (lid & 7) + ((lid & 8) ? 8 : 0);
    const uint32_t lcol = (lid & 16) ? 16u : 0u;

    for (int t = blockIdx.x; t < N_TILES; t += gridDim.x) {
        const int m0 = t * 128;
        int grow = m0 + arow; if (grow >= N_VERT) grow = N_VERT - 1;

        int idx[FE];
        #pragma unroll
        for (int f = 0; f < FE; f++) idx[f] = nidx[(long long)grow * FE + f];

        // prologue: fill taps 0..2
        #pragma unroll
        for (int f = 0; f < 3; f++) {
            const char* src = (const char*)g_xh + (size_t)idx[f] * 128 + ahf * 64;
            const uint32_t d = sb + OFF_A + (f & 3) * A_STAGE;
            #pragma unroll
            for (int j = 0; j < 4; j++)
                cp_async16(d + swz((uint32_t)(arow * 128 + ahf * 64 + j * 16)), src + j * 16);
            cp_commit();
        }

        float acc[2][4][4];
        #pragma unroll
        for (int mt = 0; mt < 2; mt++)
            #pragma unroll
            for (int nb = 0; nb < 4; nb++)
                #pragma unroll
                for (int j = 0; j < 4; j++) acc[mt][nb][j] = 0.f;

        #pragma unroll
        for (int f = 0; f < FE; f++) {
            if (f < 7)      cp_wait<2>();
            else if (f == 7) cp_wait<1>();
            else             cp_wait<0>();
            __syncthreads();   // stage f ready across all threads; prev MMAs drained

            if (f + 3 < FE) {
                const int fn = f + 3;
                const char* src = (const char*)g_xh + (size_t)idx[fn] * 128 + ahf * 64;
                const uint32_t d = sb + OFF_A + (fn & 3) * A_STAGE;
                #pragma unroll
                for (int j = 0; j < 4; j++)
                    cp_async16(d + swz((uint32_t)(arow * 128 + ahf * 64 + j * 16)), src + j * 16);
                cp_commit();
            }

            const uint32_t ab = sb + OFF_A + (f & 3) * A_STAGE;
            #pragma unroll
            for (int ks = 0; ks < 4; ks++) {
                uint32_t a[2][4];
                #pragma unroll
                for (int mt = 0; mt < 2; mt++) {
                    const int r = wm * 32 + mt * 16 + lrow8;
                    ldmatrix_x4(a[mt], ab + swz((uint32_t)(r * 128 + ks * 32 + lcol)));
                }
                #pragma unroll
                for (int nb = 0; nb < 4; nb++) {
                    const int chunk = (f * 4 + ks) * 8 + wn * 4 + nb;
                    const uint4 bf = *(const uint4*)(SB + OFF_B + (size_t)(chunk * 32 + lid) * 16);
                    #pragma unroll
                    for (int mt = 0; mt < 2; mt++) {
                        mma16816(acc[mt][nb], a[mt], bf.x, bf.y);
                        mma16816(acc[mt][nb], a[mt], bf.z, bf.w);
                    }
                }
            }
        }

        // --- epilogue: bias + direct STG ---
        const int gr = lid >> 2;
        #pragma unroll
        for (int mt = 0; mt < 2; mt++) {
            const int r0 = m0 + wm * 32 + mt * 16 + gr;
            #pragma unroll
            for (int nb = 0; nb < 4; nb++) {
                const int col = n0 + nb * 8 + qc * 2;
                if (r0 < N_VERT) {
                    float2 v; v.x = acc[mt][nb][0] + bb[nb].x;
                              v.y = acc[mt][nb][1] + bb[nb].y;
                    *(float2*)(out + (long long)r0 * NF + col) = v;
                }
                if (r0 + 8 < N_VERT) {
                    float2 v; v.x = acc[mt][nb][2] + bb[nb].x;
                              v.y = acc[mt][nb][3] + bb[nb].y;
                    *(float2*)(out + (long long)(r0 + 8) * NF + col) = v;
                }
            }
        }
        __syncthreads();   // protect A ring before next tile's prologue
    }
}

// ---------------------------------------------------------------------------
// Launch
// ---------------------------------------------------------------------------
extern "C" void kernel_launch(void* const* d_in, const int* in_sizes, int n_in,
                              void* d_out, int out_size) {
    const float* lv        = (const float*)d_in[0];
    const int*   neigh_idx = (const int*)d_in[1];
    const float* gamma     = (const float*)d_in[2];
    const float* beta      = (const float*)d_in[3];
    const float* weight    = (const float*)d_in[4];
    const float* conv_bias = (const float*)d_in[5];
    float* out = (float*)d_out;

    cudaFuncSetAttribute(gemm_mma_kernel,
                         cudaFuncAttributeMaxDynamicSharedMemorySize, SMEM_BYTES);

    stats_kernel<<<STATS_BLOCKS, STATS_THREADS>>>(lv);
    finalize_kernel<<<1, 64>>>(gamma, beta);
    convert_kernel<<<4096, 256>>>(lv);
    wfrag_kernel<<<(FE * 4 * 8 * 32 + 255) / 256, 256>>>(weight);
    gemm_mma_kernel<<<GEMM_GRID, 256, SMEM_BYTES>>>(neigh_idx, conv_bias, out);
}

// round 6
// speedup vs baseline: 6.3043x; 1.1022x over previous
#include <cuda_runtime.h>
#include <cuda_fp16.h>
#include <cstdint>

#define N_VERT 500000
#define C 64
#define FE 9
#define NF 64
#define EPS 1e-5f

#define STATS_BLOCKS 2048
#define STATS_THREADS 256
#define N_TILES ((N_VERT + 127) / 128)   // 3907
#define GEMM_GRID 148

// ---------------------------------------------------------------------------
// Device scratch (allocation-free)
// ---------------------------------------------------------------------------
__device__ float  g_partial[STATS_BLOCKS * 128];
__device__ float  g_scale[C];
__device__ float  g_shift[C];
__device__ __half g_xh[(size_t)N_VERT * C];     // fp16(relu(gn(lv)))  64 MB
// W fragments (fp16, single precision level), mma.sync B lane order.
// chunk = (f*4 + ks)*8 + nb ; index t = chunk*32 + lane ; uint2 per lane
__device__ uint4 g_wf[FE * 4 * 8 * 32 / 2];     // 9216 uint2 = 4608 uint4 = 73728 B

// SMEM layout (dynamic, 128B-aligned base)
#define OFF_B    0
#define B_BYTES  73728
#define OFF_A    73728
#define A_STAGE  16384
#define SMEM_BYTES (73728 + 4 * 16384 + 128)    // 139392

__device__ __forceinline__ uint32_t swz(uint32_t off) { return off ^ ((off >> 3) & 0x70); }

__device__ __forceinline__ uint32_t smem_u32(const void* p) {
    uint32_t a;
    asm("{ .reg .u64 t; cvta.to.shared.u64 t, %1; cvt.u32.u64 %0, t; }"
        : "=r"(a) : "l"(p));
    return a;
}
__device__ __forceinline__ void cp_async16(uint32_t dst, const void* src) {
    asm volatile("cp.async.cg.shared.global [%0], [%1], 16;"
                 :: "r"(dst), "l"(src) : "memory");
}
__device__ __forceinline__ void cp_commit() {
    asm volatile("cp.async.commit_group;" ::: "memory");
}
template <int N>
__device__ __forceinline__ void cp_wait() {
    asm volatile("cp.async.wait_group %0;" :: "n"(N) : "memory");
}
__device__ __forceinline__ void ldmatrix_x4(uint32_t* r, uint32_t addr) {
    asm volatile("ldmatrix.sync.aligned.m8n8.x4.shared.b16 {%0,%1,%2,%3}, [%4];"
                 : "=r"(r[0]), "=r"(r[1]), "=r"(r[2]), "=r"(r[3]) : "r"(addr));
}
__device__ __forceinline__ void mma16816(float* d, const uint32_t* a, uint32_t b0, uint32_t b1) {
    asm volatile(
        "mma.sync.aligned.m16n8k16.row.col.f32.f16.f16.f32 "
        "{%0,%1,%2,%3}, {%4,%5,%6,%7}, {%8,%9}, {%0,%1,%2,%3};"
        : "+f"(d[0]), "+f"(d[1]), "+f"(d[2]), "+f"(d[3])
        : "r"(a[0]), "r"(a[1]), "r"(a[2]), "r"(a[3]), "r"(b0), "r"(b1));
}

// ---------------------------------------------------------------------------
// Kernel 1: per-channel partial sums (deterministic)
// ---------------------------------------------------------------------------
__global__ void __launch_bounds__(STATS_THREADS)
stats_kernel(const float* __restrict__ lv) {
    const int tid = threadIdx.x;
    const long long total4 = (long long)N_VERT * C / 4;
    const long long stride = (long long)gridDim.x * blockDim.x;
    long long i = (long long)blockIdx.x * blockDim.x + tid;

    float sx = 0.f, sy = 0.f, sz = 0.f, sw = 0.f;
    float qx = 0.f, qy = 0.f, qz = 0.f, qw = 0.f;
    const float4* lv4 = (const float4*)lv;
    for (; i < total4; i += stride) {
        float4 v = lv4[i];
        sx += v.x; sy += v.y; sz += v.z; sw += v.w;
        qx += v.x * v.x; qy += v.y * v.y; qz += v.z * v.z; qw += v.w * v.w;
    }
    sx += __shfl_xor_sync(0xffffffffu, sx, 16);
    sy += __shfl_xor_sync(0xffffffffu, sy, 16);
    sz += __shfl_xor_sync(0xffffffffu, sz, 16);
    sw += __shfl_xor_sync(0xffffffffu, sw, 16);
    qx += __shfl_xor_sync(0xffffffffu, qx, 16);
    qy += __shfl_xor_sync(0xffffffffu, qy, 16);
    qz += __shfl_xor_sync(0xffffffffu, qz, 16);
    qw += __shfl_xor_sync(0xffffffffu, qw, 16);

    __shared__ float shs[8][64];
    __shared__ float shq[8][64];
    const int wid = tid >> 5, lane = tid & 31;
    if (lane < 16) {
        const int c0 = lane * 4;
        shs[wid][c0 + 0] = sx; shs[wid][c0 + 1] = sy;
        shs[wid][c0 + 2] = sz; shs[wid][c0 + 3] = sw;
        shq[wid][c0 + 0] = qx; shq[wid][c0 + 1] = qy;
        shq[wid][c0 + 2] = qz; shq[wid][c0 + 3] = qw;
    }
    __syncthreads();
    if (tid < 64) {
        float s = 0.f, q = 0.f;
        #pragma unroll
        for (int w = 0; w < 8; w++) { s += shs[w][tid]; q += shq[w][tid]; }
        g_partial[blockIdx.x * 128 + tid]      = s;
        g_partial[blockIdx.x * 128 + 64 + tid] = q;
    }
}

// ---------------------------------------------------------------------------
// Kernel 2: finalize -> scale/shift
// ---------------------------------------------------------------------------
__global__ void finalize_kernel(const float* __restrict__ gamma,
                                const float* __restrict__ beta) {
    const int c = threadIdx.x;
    float s = 0.f, q = 0.f;
    for (int b = 0; b < STATS_BLOCKS; b++) {
        s += g_partial[b * 128 + c];
        q += g_partial[b * 128 + 64 + c];
    }
    __shared__ float shs[64], shq[64];
    shs[c] = s; shq[c] = q;
    __syncthreads();
    const int g = c >> 1;
    const float gs = shs[2 * g] + shs[2 * g + 1];
    const float gq = shq[2 * g] + shq[2 * g + 1];
    const float inv = 1.0f / (2.0f * (float)N_VERT);
    const float mean = gs * inv;
    const float var  = gq * inv - mean * mean;
    const float rstd = rsqrtf(var + EPS);
    const float sc = rstd * gamma[c];
    g_scale[c] = sc;
    g_shift[c] = beta[c] - mean * sc;
}

// ---------------------------------------------------------------------------
// Kernel 3: xh = fp16(relu(gn(lv)))
// ---------------------------------------------------------------------------
__global__ void __launch_bounds__(256)
convert_kernel(const float* __restrict__ lv) {
    const long long total4 = (long long)N_VERT * C / 4;
    const long long stride = (long long)gridDim.x * blockDim.x;
    long long i = (long long)blockIdx.x * blockDim.x + threadIdx.x;
    const int c0 = (int)((i & 15) * 4);
    const float4 sc = *(const float4*)&g_scale[c0];
    const float4 sh = *(const float4*)&g_shift[c0];
    const float4* src = (const float4*)lv;
    uint2* dst = (uint2*)g_xh;
    for (; i < total4; i += stride) {
        float4 v = src[i];
        v.x = fmaxf(fmaf(v.x, sc.x, sh.x), 0.f);
        v.y = fmaxf(fmaf(v.y, sc.y, sh.y), 0.f);
        v.z = fmaxf(fmaf(v.z, sc.z, sh.z), 0.f);
        v.w = fmaxf(fmaf(v.w, sc.w, sh.w), 0.f);
        union { uint2 u; __half2 h[2]; } pk;
        pk.h[0] = __floats2half2_rn(v.x, v.y);
        pk.h[1] = __floats2half2_rn(v.z, v.w);
        dst[i] = pk.u;
    }
}

// ---------------------------------------------------------------------------
// Kernel 4: W -> fragment-ordered fp16
// ---------------------------------------------------------------------------
__global__ void wfrag_kernel(const float* __restrict__ W) {
    const int t = blockIdx.x * blockDim.x + threadIdx.x;
    if (t >= FE * 4 * 8 * 32) return;
    const int lane  = t & 31;
    const int chunk = t >> 5;
    const int nb = chunk & 7;
    const int ks = (chunk >> 3) & 3;
    const int f  = chunk >> 5;
    const int n  = nb * 8 + (lane >> 2);
    const int k0 = ks * 16 + 2 * (lane & 3);

    float w0 = W[(long long)(f * C + k0 + 0) * NF + n];
    float w1 = W[(long long)(f * C + k0 + 1) * NF + n];
    float w2 = W[(long long)(f * C + k0 + 8) * NF + n];
    float w3 = W[(long long)(f * C + k0 + 9) * NF + n];

    union { uint2 u; __half2 h[2]; } pk;
    pk.h[0] = __halves2half2(__float2half_rn(w0), __float2half_rn(w1));
    pk.h[1] = __halves2half2(__float2half_rn(w2), __float2half_rn(w3));
    ((uint2*)g_wf)[t] = pk.u;
}

// ---------------------------------------------------------------------------
// Kernel 5: persistent HMMA GEMM, cp.async 4-stage tap pipeline + ldmatrix.
// ---------------------------------------------------------------------------
__global__ void __launch_bounds__(256)
gemm_mma_kernel(const int* __restrict__ nidx, const float* __restrict__ bias,
                float* __restrict__ out) {
    extern __shared__ char dsm[];
    char* SB = (char*)(((uintptr_t)dsm + 127) & ~(uintptr_t)127);
    const uint32_t sb = smem_u32(SB);

    const int tid = threadIdx.x;
    const int wid = tid >> 5;
    const int lid = tid & 31;
    const int wm = wid & 3;        // m 32-block
    const int wn = wid >> 2;       // n 32-block (0/1)
    const int n0 = wn * 32;
    const int qc = lid & 3;

    // --- stage W fragments into SMEM (72 KB, once) ---
    {
        uint4* bsm = (uint4*)(SB + OFF_B);
        for (int i = tid; i < 4608; i += 256) bsm[i] = g_wf[i];
    }

    float2 bb[4];
    #pragma unroll
    for (int nb = 0; nb < 4; nb++)
        bb[nb] = *(const float2*)(bias + n0 + nb * 8 + qc * 2);

    __syncthreads();

    // gather-fill mapping: thread covers row = tid>>1, 64B half = tid&1
    const int arow = tid >> 1;
    const int ahf  = tid & 1;

    // ldmatrix per-lane address components (fixed per thread)
    const int lrow8 = (lid & 7) + ((lid & 8) ? 8 : 0);
    const uint32_t lcol = (lid & 16) ? 16u : 0u;

    for (int t = blockIdx.x; t < N_TILES; t += gridDim.x) {
        const int m0 = t * 128;
        int grow = m0 + arow; if (grow >= N_VERT) grow = N_VERT - 1;

        int idx[FE];
        #pragma unroll
        for (int f = 0; f < FE; f++) idx[f] = nidx[(long long)grow * FE + f];

        // prologue: fill taps 0..2
        #pragma unroll
        for (int f = 0; f < 3; f++) {
            const char* src = (const char*)g_xh + (size_t)idx[f] * 128 + ahf * 64;
            const uint32_t d = sb + OFF_A + (f & 3) * A_STAGE;
            #pragma unroll
            for (int j = 0; j < 4; j++)
                cp_async16(d + swz((uint32_t)(arow * 128 + ahf * 64 + j * 16)), src + j * 16);
            cp_commit();
        }

        float acc[2][4][4];
        #pragma unroll
        for (int mt = 0; mt < 2; mt++)
            #pragma unroll
            for (int nb = 0; nb < 4; nb++)
                #pragma unroll
                for (int j = 0; j < 4; j++) acc[mt][nb][j] = 0.f;

        #pragma unroll
        for (int f = 0; f < FE; f++) {
            if (f < 7)      cp_wait<2>();
            else if (f == 7) cp_wait<1>();
            else             cp_wait<0>();
            __syncthreads();   // stage f ready across all threads; prev MMAs drained

            if (f + 3 < FE) {
                const int fn = f + 3;
                const char* src = (const char*)g_xh + (size_t)idx[fn] * 128 + ahf * 64;
                const uint32_t d = sb + OFF_A + (fn & 3) * A_STAGE;
                #pragma unroll
                for (int j = 0; j < 4; j++)
                    cp_async16(d + swz((uint32_t)(arow * 128 + ahf * 64 + j * 16)), src + j * 16);
                cp_commit();
            }

            const uint32_t ab = sb + OFF_A + (f & 3) * A_STAGE;
            #pragma unroll
            for (int ks = 0; ks < 4; ks++) {
                uint32_t a[2][4];
                #pragma unroll
                for (int mt = 0; mt < 2; mt++) {
                    const int r = wm * 32 + mt * 16 + lrow8;
                    ldmatrix_x4(a[mt], ab + swz((uint32_t)(r * 128 + ks * 32 + lcol)));
                }
                #pragma unroll
                for (int nb = 0; nb < 4; nb++) {
                    const int chunk = (f * 4 + ks) * 8 + wn * 4 + nb;
                    const uint2 bf = *(const uint2*)(SB + OFF_B + (size_t)(chunk * 32 + lid) * 8);
                    #pragma unroll
                    for (int mt = 0; mt < 2; mt++)
                        mma16816(acc[mt][nb], a[mt], bf.x, bf.y);
                }
            }
        }

        // --- epilogue: bias + direct STG ---
        const int gr = lid >> 2;
        #pragma unroll
        for (int mt = 0; mt < 2; mt++) {
            const int r0 = m0 + wm * 32 + mt * 16 + gr;
            #pragma unroll
            for (int nb = 0; nb < 4; nb++) {
                const int col = n0 + nb * 8 + qc * 2;
                if (r0 < N_VERT) {
                    float2 v; v.x = acc[mt][nb][0] + bb[nb].x;
                              v.y = acc[mt][nb][1] + bb[nb].y;
                    *(float2*)(out + (long long)r0 * NF + col) = v;
                }
                if (r0 + 8 < N_VERT) {
                    float2 v; v.x = acc[mt][nb][2] + bb[nb].x;
                              v.y = acc[mt][nb][3] + bb[nb].y;
                    *(float2*)(out + (long long)(r0 + 8) * NF + col) = v;
                }
            }
        }
        __syncthreads();   // protect A ring before next tile's prologue
    }
}

// ---------------------------------------------------------------------------
// Launch
// ---------------------------------------------------------------------------
extern "C" void kernel_launch(void* const* d_in, const int* in_sizes, int n_in,
                              void* d_out, int out_size) {
    const float* lv        = (const float*)d_in[0];
    const int*   neigh_idx = (const int*)d_in[1];
    const float* gamma     = (const float*)d_in[2];
    const float* beta      = (const float*)d_in[3];
    const float* weight    = (const float*)d_in[4];
    const float* conv_bias = (const float*)d_in[5];
    float* out = (float*)d_out;

    cudaFuncSetAttribute(gemm_mma_kernel,
                         cudaFuncAttributeMaxDynamicSharedMemorySize, SMEM_BYTES);

    stats_kernel<<<STATS_BLOCKS, STATS_THREADS>>>(lv);
    finalize_kernel<<<1, 64>>>(gamma, beta);
    convert_kernel<<<4096, 256>>>(lv);
    wfrag_kernel<<<(FE * 4 * 8 * 32 + 255) / 256, 256>>>(weight);
    gemm_mma_kernel<<<GEMM_GRID, 256, SMEM_BYTES>>>(neigh_idx, conv_bias, out);
}

// round 7
// speedup vs baseline: 6.6034x; 1.0474x over previous
#include <cuda_runtime.h>
#include <cuda_fp16.h>
#include <cstdint>

#define N_VERT 500000
#define C 64
#define FE 9
#define NF 64
#define EPS 1e-5f

#define STATS_BLOCKS 2048
#define STATS_THREADS 256
#define TILE_M 64
#define N_TILES ((N_VERT + TILE_M - 1) / TILE_M)   // 7813
#define GEMM_GRID (2 * 148)                        // 2 CTAs per SM

// ---------------------------------------------------------------------------
// Device scratch (allocation-free)
// ---------------------------------------------------------------------------
__device__ float  g_partial[STATS_BLOCKS * 128];
__device__ float  g_scale[C];
__device__ float  g_shift[C];
__device__ __half g_xh[(size_t)N_VERT * C];     // fp16(relu(gn(lv)))  64 MB
// W fragments (fp16), mma.sync B lane order.
// chunk = (f*4 + ks)*8 + nb ; index t = chunk*32 + lane ; uint2 per lane
__device__ uint4 g_wf[FE * 4 * 8 * 32 / 2];     // 4608 uint4 = 73728 B

// SMEM layout (dynamic, 128B-aligned base), per CTA
#define OFF_B    0
#define OFF_A    73728
#define A_STAGE  8192                       // 64 rows x 128 B
#define SMEM_BYTES (73728 + 4 * 8192 + 128) // 106624 -> 2 CTAs/SM

__device__ __forceinline__ uint32_t swz(uint32_t off) { return off ^ ((off >> 3) & 0x70); }

__device__ __forceinline__ uint32_t smem_u32(const void* p) {
    uint32_t a;
    asm("{ .reg .u64 t; cvta.to.shared.u64 t, %1; cvt.u32.u64 %0, t; }"
        : "=r"(a) : "l"(p));
    return a;
}
__device__ __forceinline__ void cp_async16(uint32_t dst, const void* src) {
    asm volatile("cp.async.cg.shared.global [%0], [%1], 16;"
                 :: "r"(dst), "l"(src) : "memory");
}
__device__ __forceinline__ void cp_commit() {
    asm volatile("cp.async.commit_group;" ::: "memory");
}
template <int N>
__device__ __forceinline__ void cp_wait() {
    asm volatile("cp.async.wait_group %0;" :: "n"(N) : "memory");
}
__device__ __forceinline__ void ldmatrix_x4(uint32_t* r, uint32_t addr) {
    asm volatile("ldmatrix.sync.aligned.m8n8.x4.shared.b16 {%0,%1,%2,%3}, [%4];"
                 : "=r"(r[0]), "=r"(r[1]), "=r"(r[2]), "=r"(r[3]) : "r"(addr));
}
__device__ __forceinline__ void mma16816(float* d, const uint32_t* a, uint32_t b0, uint32_t b1) {
    asm volatile(
        "mma.sync.aligned.m16n8k16.row.col.f32.f16.f16.f32 "
        "{%0,%1,%2,%3}, {%4,%5,%6,%7}, {%8,%9}, {%0,%1,%2,%3};"
        : "+f"(d[0]), "+f"(d[1]), "+f"(d[2]), "+f"(d[3])
        : "r"(a[0]), "r"(a[1]), "r"(a[2]), "r"(a[3]), "r"(b0), "r"(b1));
}

// ---------------------------------------------------------------------------
// Kernel 1: per-channel partial sums (deterministic)
// ---------------------------------------------------------------------------
__global__ void __launch_bounds__(STATS_THREADS)
stats_kernel(const float* __restrict__ lv) {
    const int tid = threadIdx.x;
    const long long total4 = (long long)N_VERT * C / 4;
    const long long stride = (long long)gridDim.x * blockDim.x;
    long long i = (long long)blockIdx.x * blockDim.x + tid;

    float sx = 0.f, sy = 0.f, sz = 0.f, sw = 0.f;
    float qx = 0.f, qy = 0.f, qz = 0.f, qw = 0.f;
    const float4* lv4 = (const float4*)lv;
    for (; i < total4; i += stride) {
        float4 v = lv4[i];
        sx += v.x; sy += v.y; sz += v.z; sw += v.w;
        qx += v.x * v.x; qy += v.y * v.y; qz += v.z * v.z; qw += v.w * v.w;
    }
    sx += __shfl_xor_sync(0xffffffffu, sx, 16);
    sy += __shfl_xor_sync(0xffffffffu, sy, 16);
    sz += __shfl_xor_sync(0xffffffffu, sz, 16);
    sw += __shfl_xor_sync(0xffffffffu, sw, 16);
    qx += __shfl_xor_sync(0xffffffffu, qx, 16);
    qy += __shfl_xor_sync(0xffffffffu, qy, 16);
    qz += __shfl_xor_sync(0xffffffffu, qz, 16);
    qw += __shfl_xor_sync(0xffffffffu, qw, 16);

    __shared__ float shs[8][64];
    __shared__ float shq[8][64];
    const int wid = tid >> 5, lane = tid & 31;
    if (lane < 16) {
        const int c0 = lane * 4;
        shs[wid][c0 + 0] = sx; shs[wid][c0 + 1] = sy;
        shs[wid][c0 + 2] = sz; shs[wid][c0 + 3] = sw;
        shq[wid][c0 + 0] = qx; shq[wid][c0 + 1] = qy;
        shq[wid][c0 + 2] = qz; shq[wid][c0 + 3] = qw;
    }
    __syncthreads();
    if (tid < 64) {
        float s = 0.f, q = 0.f;
        #pragma unroll
        for (int w = 0; w < 8; w++) { s += shs[w][tid]; q += shq[w][tid]; }
        g_partial[blockIdx.x * 128 + tid]      = s;
        g_partial[blockIdx.x * 128 + 64 + tid] = q;
    }
}

// ---------------------------------------------------------------------------
// Kernel 2: finalize -> scale/shift
// ---------------------------------------------------------------------------
__global__ void finalize_kernel(const float* __restrict__ gamma,
                                const float* __restrict__ beta) {
    const int c = threadIdx.x;
    float s = 0.f, q = 0.f;
    for (int b = 0; b < STATS_BLOCKS; b++) {
        s += g_partial[b * 128 + c];
        q += g_partial[b * 128 + 64 + c];
    }
    __shared__ float shs[64], shq[64];
    shs[c] = s; shq[c] = q;
    __syncthreads();
    const int g = c >> 1;
    const float gs = shs[2 * g] + shs[2 * g + 1];
    const float gq = shq[2 * g] + shq[2 * g + 1];
    const float inv = 1.0f / (2.0f * (float)N_VERT);
    const float mean = gs * inv;
    const float var  = gq * inv - mean * mean;
    const float rstd = rsqrtf(var + EPS);
    const float sc = rstd * gamma[c];
    g_scale[c] = sc;
    g_shift[c] = beta[c] - mean * sc;
}

// ---------------------------------------------------------------------------
// Kernel 3: xh = fp16(relu(gn(lv)))
// ---------------------------------------------------------------------------
__global__ void __launch_bounds__(256)
convert_kernel(const float* __restrict__ lv) {
    const long long total4 = (long long)N_VERT * C / 4;
    const long long stride = (long long)gridDim.x * blockDim.x;
    long long i = (long long)blockIdx.x * blockDim.x + threadIdx.x;
    const int c0 = (int)((i & 15) * 4);
    const float4 sc = *(const float4*)&g_scale[c0];
    const float4 sh = *(const float4*)&g_shift[c0];
    const float4* src = (const float4*)lv;
    uint2* dst = (uint2*)g_xh;
    for (; i < total4; i += stride) {
        float4 v = src[i];
        v.x = fmaxf(fmaf(v.x, sc.x, sh.x), 0.f);
        v.y = fmaxf(fmaf(v.y, sc.y, sh.y), 0.f);
        v.z = fmaxf(fmaf(v.z, sc.z, sh.z), 0.f);
        v.w = fmaxf(fmaf(v.w, sc.w, sh.w), 0.f);
        union { uint2 u; __half2 h[2]; } pk;
        pk.h[0] = __floats2half2_rn(v.x, v.y);
        pk.h[1] = __floats2half2_rn(v.z, v.w);
        dst[i] = pk.u;
    }
}

// ---------------------------------------------------------------------------
// Kernel 4: W -> fragment-ordered fp16
// ---------------------------------------------------------------------------
__global__ void wfrag_kernel(const float* __restrict__ W) {
    const int t = blockIdx.x * blockDim.x + threadIdx.x;
    if (t >= FE * 4 * 8 * 32) return;
    const int lane  = t & 31;
    const int chunk = t >> 5;
    const int nb = chunk & 7;
    const int ks = (chunk >> 3) & 3;
    const int f  = chunk >> 5;
    const int n  = nb * 8 + (lane >> 2);
    const int k0 = ks * 16 + 2 * (lane & 3);

    float w0 = W[(long long)(f * C + k0 + 0) * NF + n];
    float w1 = W[(long long)(f * C + k0 + 1) * NF + n];
    float w2 = W[(long long)(f * C + k0 + 8) * NF + n];
    float w3 = W[(long long)(f * C + k0 + 9) * NF + n];

    union { uint2 u; __half2 h[2]; } pk;
    pk.h[0] = __halves2half2(__float2half_rn(w0), __float2half_rn(w1));
    pk.h[1] = __halves2half2(__float2half_rn(w2), __float2half_rn(w3));
    ((uint2*)g_wf)[t] = pk.u;
}

// ---------------------------------------------------------------------------
// Kernel 5: persistent HMMA GEMM, M=64 tiles, 2 CTAs/SM, cp.async pipeline.
// 128 threads = 4 warps; warp (wm = wid&1, wn = wid>>1) owns out[wm*32.., wn*32..]
// ---------------------------------------------------------------------------
__global__ void __launch_bounds__(128)
gemm_mma_kernel(const int* __restrict__ nidx, const float* __restrict__ bias,
                float* __restrict__ out) {
    extern __shared__ char dsm[];
    char* SB = (char*)(((uintptr_t)dsm + 127) & ~(uintptr_t)127);
    const uint32_t sb = smem_u32(SB);

    const int tid = threadIdx.x;
    const int wid = tid >> 5;
    const int lid = tid & 31;
    const int wm = wid & 1;        // m 32-block (0/1)
    const int wn = wid >> 1;       // n 32-block (0/1)
    const int n0 = wn * 32;
    const int qc = lid & 3;

    // --- stage W fragments into SMEM (72 KB, once) ---
    {
        uint4* bsm = (uint4*)(SB + OFF_B);
        for (int i = tid; i < 4608; i += 128) bsm[i] = g_wf[i];
    }

    float2 bb[4];
    #pragma unroll
    for (int nb = 0; nb < 4; nb++)
        bb[nb] = *(const float2*)(bias + n0 + nb * 8 + qc * 2);

    __syncthreads();

    // gather-fill mapping: thread covers row = tid>>1 (0..63), 64B half = tid&1
    const int arow = tid >> 1;
    const int ahf  = tid & 1;

    // ldmatrix per-lane address components
    const int lrow8 = (lid & 7) + ((lid & 8) ? 8 : 0);
    const uint32_t lcol = (lid & 16) ? 16u : 0u;

    for (int t = blockIdx.x; t < N_TILES; t += gridDim.x) {
        const int m0 = t * TILE_M;
        int grow = m0 + arow; if (grow >= N_VERT) grow = N_VERT - 1;

        int idx[FE];
        #pragma unroll
        for (int f = 0; f < FE; f++) idx[f] = nidx[(long long)grow * FE + f];

        // prologue: fill taps 0..2
        #pragma unroll
        for (int f = 0; f < 3; f++) {
            const char* src = (const char*)g_xh + (size_t)idx[f] * 128 + ahf * 64;
            const uint32_t d = sb + OFF_A + (f & 3) * A_STAGE;
            #pragma unroll
            for (int j = 0; j < 4; j++)
                cp_async16(d + swz((uint32_t)(arow * 128 + ahf * 64 + j * 16)), src + j * 16);
            cp_commit();
        }

        float acc[2][4][4];
        #pragma unroll
        for (int mt = 0; mt < 2; mt++)
            #pragma unroll
            for (int nb = 0; nb < 4; nb++)
                #pragma unroll
                for (int j = 0; j < 4; j++) acc[mt][nb][j] = 0.f;

        #pragma unroll
        for (int f = 0; f < FE; f++) {
            if (f < 7)       cp_wait<2>();
            else if (f == 7) cp_wait<1>();
            else             cp_wait<0>();
            __syncthreads();   // stage f ready across all threads; prev MMAs drained

            if (f + 3 < FE) {
                const int fn = f + 3;
                const char* src = (const char*)g_xh + (size_t)idx[fn] * 128 + ahf * 64;
                const uint32_t d = sb + OFF_A + (fn & 3) * A_STAGE;
                #pragma unroll
                for (int j = 0; j < 4; j++)
                    cp_async16(d + swz((uint32_t)(arow * 128 + ahf * 64 + j * 16)), src + j * 16);
                cp_commit();
            }

            const uint32_t ab = sb + OFF_A + (f & 3) * A_STAGE;
            #pragma unroll
            for (int ks = 0; ks < 4; ks++) {
                uint32_t a[2][4];
                #pragma unroll
                for (int mt = 0; mt < 2; mt++) {
                    const int r = wm * 32 + mt * 16 + lrow8;
                    ldmatrix_x4(a[mt], ab + swz((uint32_t)(r * 128 + ks * 32 + lcol)));
                }
                #pragma unroll
                for (int nb = 0; nb < 4; nb++) {
                    const int chunk = (f * 4 + ks) * 8 + wn * 4 + nb;
                    const uint2 bf = *(const uint2*)(SB + OFF_B + (size_t)(chunk * 32 + lid) * 8);
                    #pragma unroll
                    for (int mt = 0; mt < 2; mt++)
                        mma16816(acc[mt][nb], a[mt], bf.x, bf.y);
                }
            }
        }

        // --- epilogue: bias + direct STG ---
        const int gr = lid >> 2;
        #pragma unroll
        for (int mt = 0; mt < 2; mt++) {
            const int r0 = m0 + wm * 32 + mt * 16 + gr;
            #pragma unroll
            for (int nb = 0; nb < 4; nb++) {
                const int col = n0 + nb * 8 + qc * 2;
                if (r0 < N_VERT) {
                    float2 v; v.x = acc[mt][nb][0] + bb[nb].x;
                              v.y = acc[mt][nb][1] + bb[nb].y;
                    *(float2*)(out + (long long)r0 * NF + col) = v;
                }
                if (r0 + 8 < N_VERT) {
                    float2 v; v.x = acc[mt][nb][2] + bb[nb].x;
                              v.y = acc[mt][nb][3] + bb[nb].y;
                    *(float2*)(out + (long long)(r0 + 8) * NF + col) = v;
                }
            }
        }
        __syncthreads();   // protect A ring before next tile's prologue
    }
}

// ---------------------------------------------------------------------------
// Launch
// ---------------------------------------------------------------------------
extern "C" void kernel_launch(void* const* d_in, const int* in_sizes, int n_in,
                              void* d_out, int out_size) {
    const float* lv        = (const float*)d_in[0];
    const int*   neigh_idx = (const int*)d_in[1];
    const float* gamma     = (const float*)d_in[2];
    const float* beta      = (const float*)d_in[3];
    const float* weight    = (const float*)d_in[4];
    const float* conv_bias = (const float*)d_in[5];
    float* out = (float*)d_out;

    cudaFuncSetAttribute(gemm_mma_kernel,
                         cudaFuncAttributeMaxDynamicSharedMemorySize, SMEM_BYTES);

    stats_kernel<<<STATS_BLOCKS, STATS_THREADS>>>(lv);
    finalize_kernel<<<1, 64>>>(gamma, beta);
    convert_kernel<<<4096, 256>>>(lv);
    wfrag_kernel<<<(FE * 4 * 8 * 32 + 255) / 256, 256>>>(weight);
    gemm_mma_kernel<<<GEMM_GRID, 128, SMEM_BYTES>>>(neigh_idx, conv_bias, out);
}

// round 8
// speedup vs baseline: 7.8292x; 1.1856x over previous
#include <cuda_runtime.h>
#include <cuda_fp16.h>
#include <cstdint>

#define N_VERT 500000
#define C 64
#define FE 9
#define NF 64
#define EPS 1e-5f

#define STATS_BLOCKS 2048
#define STATS_THREADS 256
#define TILE_M 64
#define N_TILES ((N_VERT + TILE_M - 1) / TILE_M)   // 7813
#define GEMM_GRID (2 * 148)                        // 2 CTAs per SM

// ---------------------------------------------------------------------------
// Device scratch (allocation-free)
// ---------------------------------------------------------------------------
__device__ float  g_partial[STATS_BLOCKS * 128];
__device__ float  g_scale[C];
__device__ float  g_shift[C];
__device__ __half g_xh[(size_t)N_VERT * C];     // fp16(relu(gn(lv)))  64 MB
// W fragments (fp16), mma.sync B lane order.
// chunk = (f*4 + ks)*8 + nb ; index t = chunk*32 + lane ; uint2 per lane
__device__ uint4 g_wf[FE * 4 * 8 * 32 / 2];     // 4608 uint4 = 73728 B

// SMEM layout (dynamic, 128B-aligned base), per CTA
#define OFF_B    0
#define OFF_A    73728                       // per-warp rings follow B
#define WARP_RING 8192                       // 4 stages x 16 rows x 128 B
#define A_STAGE  2048
#define SMEM_BYTES (73728 + 4 * 8192 + 128)  // 106624 -> 2 CTAs/SM

__device__ __forceinline__ uint32_t swz(uint32_t off) { return off ^ ((off >> 3) & 0x70); }

__device__ __forceinline__ uint32_t smem_u32(const void* p) {
    uint32_t a;
    asm("{ .reg .u64 t; cvta.to.shared.u64 t, %1; cvt.u32.u64 %0, t; }"
        : "=r"(a) : "l"(p));
    return a;
}
__device__ __forceinline__ void cp_async16(uint32_t dst, const void* src) {
    asm volatile("cp.async.cg.shared.global [%0], [%1], 16;"
                 :: "r"(dst), "l"(src) : "memory");
}
__device__ __forceinline__ void cp_commit() {
    asm volatile("cp.async.commit_group;" ::: "memory");
}
template <int N>
__device__ __forceinline__ void cp_wait() {
    asm volatile("cp.async.wait_group %0;" :: "n"(N) : "memory");
}
__device__ __forceinline__ void ldmatrix_x4(uint32_t* r, uint32_t addr) {
    asm volatile("ldmatrix.sync.aligned.m8n8.x4.shared.b16 {%0,%1,%2,%3}, [%4];"
                 : "=r"(r[0]), "=r"(r[1]), "=r"(r[2]), "=r"(r[3]) : "r"(addr));
}
__device__ __forceinline__ void mma16816(float* d, const uint32_t* a, uint32_t b0, uint32_t b1) {
    asm volatile(
        "mma.sync.aligned.m16n8k16.row.col.f32.f16.f16.f32 "
        "{%0,%1,%2,%3}, {%4,%5,%6,%7}, {%8,%9}, {%0,%1,%2,%3};"
        : "+f"(d[0]), "+f"(d[1]), "+f"(d[2]), "+f"(d[3])
        : "r"(a[0]), "r"(a[1]), "r"(a[2]), "r"(a[3]), "r"(b0), "r"(b1));
}

// ---------------------------------------------------------------------------
// Kernel 1: per-channel partial sums (deterministic)
// ---------------------------------------------------------------------------
__global__ void __launch_bounds__(STATS_THREADS)
stats_kernel(const float* __restrict__ lv) {
    const int tid = threadIdx.x;
    const long long total4 = (long long)N_VERT * C / 4;
    const long long stride = (long long)gridDim.x * blockDim.x;
    long long i = (long long)blockIdx.x * blockDim.x + tid;

    float sx = 0.f, sy = 0.f, sz = 0.f, sw = 0.f;
    float qx = 0.f, qy = 0.f, qz = 0.f, qw = 0.f;
    const float4* lv4 = (const float4*)lv;
    for (; i < total4; i += stride) {
        float4 v = lv4[i];
        sx += v.x; sy += v.y; sz += v.z; sw += v.w;
        qx += v.x * v.x; qy += v.y * v.y; qz += v.z * v.z; qw += v.w * v.w;
    }
    sx += __shfl_xor_sync(0xffffffffu, sx, 16);
    sy += __shfl_xor_sync(0xffffffffu, sy, 16);
    sz += __shfl_xor_sync(0xffffffffu, sz, 16);
    sw += __shfl_xor_sync(0xffffffffu, sw, 16);
    qx += __shfl_xor_sync(0xffffffffu, qx, 16);
    qy += __shfl_xor_sync(0xffffffffu, qy, 16);
    qz += __shfl_xor_sync(0xffffffffu, qz, 16);
    qw += __shfl_xor_sync(0xffffffffu, qw, 16);

    __shared__ float shs[8][64];
    __shared__ float shq[8][64];
    const int wid = tid >> 5, lane = tid & 31;
    if (lane < 16) {
        const int c0 = lane * 4;
        shs[wid][c0 + 0] = sx; shs[wid][c0 + 1] = sy;
        shs[wid][c0 + 2] = sz; shs[wid][c0 + 3] = sw;
        shq[wid][c0 + 0] = qx; shq[wid][c0 + 1] = qy;
        shq[wid][c0 + 2] = qz; shq[wid][c0 + 3] = qw;
    }
    __syncthreads();
    if (tid < 64) {
        float s = 0.f, q = 0.f;
        #pragma unroll
        for (int w = 0; w < 8; w++) { s += shs[w][tid]; q += shq[w][tid]; }
        g_partial[blockIdx.x * 128 + tid]      = s;
        g_partial[blockIdx.x * 128 + 64 + tid] = q;
    }
}

// ---------------------------------------------------------------------------
// Kernel 2: finalize -> scale/shift
// ---------------------------------------------------------------------------
__global__ void finalize_kernel(const float* __restrict__ gamma,
                                const float* __restrict__ beta) {
    const int c = threadIdx.x;
    float s = 0.f, q = 0.f;
    for (int b = 0; b < STATS_BLOCKS; b++) {
        s += g_partial[b * 128 + c];
        q += g_partial[b * 128 + 64 + c];
    }
    __shared__ float shs[64], shq[64];
    shs[c] = s; shq[c] = q;
    __syncthreads();
    const int g = c >> 1;
    const float gs = shs[2 * g] + shs[2 * g + 1];
    const float gq = shq[2 * g] + shq[2 * g + 1];
    const float inv = 1.0f / (2.0f * (float)N_VERT);
    const float mean = gs * inv;
    const float var  = gq * inv - mean * mean;
    const float rstd = rsqrtf(var + EPS);
    const float sc = rstd * gamma[c];
    g_scale[c] = sc;
    g_shift[c] = beta[c] - mean * sc;
}

// ---------------------------------------------------------------------------
// Kernel 3: xh = fp16(relu(gn(lv)))
// ---------------------------------------------------------------------------
__global__ void __launch_bounds__(256)
convert_kernel(const float* __restrict__ lv) {
    const long long total4 = (long long)N_VERT * C / 4;
    const long long stride = (long long)gridDim.x * blockDim.x;
    long long i = (long long)blockIdx.x * blockDim.x + threadIdx.x;
    const int c0 = (int)((i & 15) * 4);
    const float4 sc = *(const float4*)&g_scale[c0];
    const float4 sh = *(const float4*)&g_shift[c0];
    const float4* src = (const float4*)lv;
    uint2* dst = (uint2*)g_xh;
    for (; i < total4; i += stride) {
        float4 v = src[i];
        v.x = fmaxf(fmaf(v.x, sc.x, sh.x), 0.f);
        v.y = fmaxf(fmaf(v.y, sc.y, sh.y), 0.f);
        v.z = fmaxf(fmaf(v.z, sc.z, sh.z), 0.f);
        v.w = fmaxf(fmaf(v.w, sc.w, sh.w), 0.f);
        union { uint2 u; __half2 h[2]; } pk;
        pk.h[0] = __floats2half2_rn(v.x, v.y);
        pk.h[1] = __floats2half2_rn(v.z, v.w);
        dst[i] = pk.u;
    }
}

// ---------------------------------------------------------------------------
// Kernel 4: W -> fragment-ordered fp16
// ---------------------------------------------------------------------------
__global__ void wfrag_kernel(const float* __restrict__ W) {
    const int t = blockIdx.x * blockDim.x + threadIdx.x;
    if (t >= FE * 4 * 8 * 32) return;
    const int lane  = t & 31;
    const int chunk = t >> 5;
    const int nb = chunk & 7;
    const int ks = (chunk >> 3) & 3;
    const int f  = chunk >> 5;
    const int n  = nb * 8 + (lane >> 2);
    const int k0 = ks * 16 + 2 * (lane & 3);

    float w0 = W[(long long)(f * C + k0 + 0) * NF + n];
    float w1 = W[(long long)(f * C + k0 + 1) * NF + n];
    float w2 = W[(long long)(f * C + k0 + 8) * NF + n];
    float w3 = W[(long long)(f * C + k0 + 9) * NF + n];

    union { uint2 u; __half2 h[2]; } pk;
    pk.h[0] = __halves2half2(__float2half_rn(w0), __float2half_rn(w1));
    pk.h[1] = __halves2half2(__float2half_rn(w2), __float2half_rn(w3));
    ((uint2*)g_wf)[t] = pk.u;
}

// ---------------------------------------------------------------------------
// Kernel 5: persistent HMMA GEMM, warp-independent pipelines.
// Each warp owns a 16-row strip x full N=64; per-warp 4-stage cp.async ring;
// no block barriers in the main loop; cross-tile pipelining.
// ---------------------------------------------------------------------------
__global__ void __launch_bounds__(128)
gemm_mma_kernel(const int* __restrict__ nidx, const float* __restrict__ bias,
                float* __restrict__ out) {
    extern __shared__ char dsm[];
    char* SB = (char*)(((uintptr_t)dsm + 127) & ~(uintptr_t)127);
    const uint32_t sb = smem_u32(SB);

    const int tid = threadIdx.x;
    const int wid = tid >> 5;
    const int lid = tid & 31;
    const int qc = lid & 3;
    const int gr = lid >> 2;

    // --- stage W fragments into SMEM (72 KB, once) ---
    {
        uint4* bsm = (uint4*)(SB + OFF_B);
        for (int i = tid; i < 4608; i += 128) bsm[i] = g_wf[i];
    }
    __syncthreads();

    float2 bb[8];
    #pragma unroll
    for (int nb = 0; nb < 8; nb++)
        bb[nb] = *(const float2*)(bias + nb * 8 + qc * 2);

    // gather mapping: lane covers local row rl = lid>>1 (0..15), 64B half hf
    const int rl = lid >> 1;
    const int hf = lid & 1;
    const uint32_t fill_off = (uint32_t)(rl * 128 + hf * 64);
    const uint32_t ring = sb + OFF_A + wid * WARP_RING;

    // ldmatrix lane address components
    const int lrow8 = (lid & 7) + ((lid & 8) ? 8 : 0);
    const uint32_t lcol = (lid & 16) ? 16u : 0u;

    int t = blockIdx.x;
    if (t >= N_TILES) return;

    // --- warp prologue: idx for first tile, fill taps 0..2 ---
    int idxCur[FE], idxNxt[FE];
    {
        int grow = t * TILE_M + wid * 16 + rl;
        if (grow >= N_VERT) grow = N_VERT - 1;
        #pragma unroll
        for (int f = 0; f < FE; f++) idxCur[f] = nidx[(long long)grow * FE + f];
    }
    #pragma unroll
    for (int f = 0; f < 3; f++) {
        const char* src = (const char*)g_xh + (size_t)idxCur[f] * 128 + hf * 64;
        const uint32_t d = ring + (uint32_t)f * A_STAGE;
        #pragma unroll
        for (int j = 0; j < 4; j++)
            cp_async16(d + swz(fill_off + j * 16), src + j * 16);
        cp_commit();
    }

    int st = 0;  // ring stage of current tap

    for (; t < N_TILES; t += GEMM_GRID) {
        const bool last = (t + GEMM_GRID >= N_TILES);
        const int m0 = t * TILE_M;
        const int strip = m0 + wid * 16;

        // prefetch next tile's indices (used from slot f==6)
        if (!last) {
            int grow2 = (t + GEMM_GRID) * TILE_M + wid * 16 + rl;
            if (grow2 >= N_VERT) grow2 = N_VERT - 1;
            #pragma unroll
            for (int f = 0; f < FE; f++) idxNxt[f] = nidx[(long long)grow2 * FE + f];
        }

        float acc[8][4];
        #pragma unroll
        for (int nb = 0; nb < 8; nb++)
            #pragma unroll
            for (int j = 0; j < 4; j++) acc[nb][j] = 0.f;

        #pragma unroll
        for (int f = 0; f < FE; f++) {
            if (!last || f < 7) cp_wait<2>();
            else if (f == 7)    cp_wait<1>();
            else                cp_wait<0>();
            __syncwarp();

            // fill slot: tap f+3 of this tile, or tap f-6 of next tile
            {
                const int gf = f + 3;
                int fidx = -1;
                if (gf < FE)        fidx = idxCur[gf];
                else if (!last)     fidx = idxNxt[gf - FE];
                if (fidx >= 0) {
                    const char* src = (const char*)g_xh + (size_t)fidx * 128 + hf * 64;
                    const uint32_t d = ring + (uint32_t)((st + 3) & 3) * A_STAGE;
                    #pragma unroll
                    for (int j = 0; j < 4; j++)
                        cp_async16(d + swz(fill_off + j * 16), src + j * 16);
                    cp_commit();
                }
            }

            // compute tap f from stage st
            const uint32_t ab = ring + (uint32_t)st * A_STAGE;
            #pragma unroll
            for (int ks = 0; ks < 4; ks++) {
                uint32_t a[4];
                ldmatrix_x4(a, ab + swz((uint32_t)(lrow8 * 128 + ks * 32 + lcol)));
                #pragma unroll
                for (int nb = 0; nb < 8; nb++) {
                    const int chunk = (f * 4 + ks) * 8 + nb;
                    const uint2 bf = *(const uint2*)(SB + OFF_B + (size_t)(chunk * 32 + lid) * 8);
                    mma16816(acc[nb], a, bf.x, bf.y);
                }
            }
            st = (st + 1) & 3;
        }

        // --- epilogue: bias + direct STG (warp-private rows) ---
        {
            const int r0 = strip + gr;
            #pragma unroll
            for (int nb = 0; nb < 8; nb++) {
                const int col = nb * 8 + qc * 2;
                if (r0 < N_VERT) {
                    float2 v; v.x = acc[nb][0] + bb[nb].x;
                              v.y = acc[nb][1] + bb[nb].y;
                    *(float2*)(out + (long long)r0 * NF + col) = v;
                }
                if (r0 + 8 < N_VERT) {
                    float2 v; v.x = acc[nb][2] + bb[nb].x;
                              v.y = acc[nb][3] + bb[nb].y;
                    *(float2*)(out + (long long)(r0 + 8) * NF + col) = v;
                }
            }
        }

        // rotate idx buffers
        #pragma unroll
        for (int f = 0; f < FE; f++) idxCur[f] = idxNxt[f];
    }
}

// ---------------------------------------------------------------------------
// Launch
// ---------------------------------------------------------------------------
extern "C" void kernel_launch(void* const* d_in, const int* in_sizes, int n_in,
                              void* d_out, int out_size) {
    const float* lv        = (const float*)d_in[0];
    const int*   neigh_idx = (const int*)d_in[1];
    const float* gamma     = (const float*)d_in[2];
    const float* beta      = (const float*)d_in[3];
    const float* weight    = (const float*)d_in[4];
    const float* conv_bias = (const float*)d_in[5];
    float* out = (float*)d_out;

    cudaFuncSetAttribute(gemm_mma_kernel,
                         cudaFuncAttributeMaxDynamicSharedMemorySize, SMEM_BYTES);

    stats_kernel<<<STATS_BLOCKS, STATS_THREADS>>>(lv);
    finalize_kernel<<<1, 64>>>(gamma, beta);
    convert_kernel<<<4096, 256>>>(lv);
    wfrag_kernel<<<(FE * 4 * 8 * 32 + 255) / 256, 256>>>(weight);
    gemm_mma_kernel<<<GEMM_GRID, 128, SMEM_BYTES>>>(neigh_idx, conv_bias, out);
}